// round 4
// baseline (speedup 1.0000x reference)
#include <cuda_runtime.h>
#include <cuda_bf16.h>
#include <cstdint>

// Problem constants (from reference): T=2, N=50000, E=800000, C=128
#define TT 2
#define MAXN 50000
#define MAXE 800000
#define CDIM 128

// Scratch (device globals: allocation-free rule). float4 arrays force 16B alignment.
__device__ float4 g_h[MAXN * (CDIM / 4)];    // 25.6 MB  (X @ W product)
__device__ float4 g_agg[MAXN * (CDIM / 4)];  // 25.6 MB  (aggregation accumulator)
__device__ float  g_dinv[MAXN];              // rsqrt(deg)
__device__ int    g_eidx[TT * 2 * MAXE];     // 12.8 MB  (edge indices as int32)
__device__ int    g_is64;                    // 1 if input edge dtype is int64

// Vector reduction: native float4 atomicAdd (CUDA >= 12.8, sm_90+).
__device__ __forceinline__ void red_add_f4(float4* p, float4 v) {
#if defined(__CUDA_ARCH__) && (__CUDA_ARCH__ >= 900) && defined(CUDART_VERSION) && (CUDART_VERSION >= 12080)
    atomicAdd(p, v);
#else
    float* f = reinterpret_cast<float*>(p);
    atomicAdd(f + 0, v.x);
    atomicAdd(f + 1, v.y);
    atomicAdd(f + 2, v.z);
    atomicAdd(f + 3, v.w);
#endif
}

// ---------------------------------------------------------------------------
// Edge-index dtype detection + conversion to int32
// ---------------------------------------------------------------------------
// If the raw buffer is int64 (little-endian, values in [0, N)), every odd
// 32-bit word of the first elements is 0. If it is int32, those words are
// random indices -> essentially never all zero.
__global__ void k_detect(const unsigned int* __restrict__ raw, int total_elems) {
    if (blockIdx.x == 0 && threadIdx.x == 0) {
        int n = total_elems < 64 ? total_elems : 64;
        int all0 = 1;
        for (int i = 0; i < n; i++)
            if (raw[2 * i + 1] != 0u) { all0 = 0; break; }
        g_is64 = all0;
    }
}

__global__ void k_convert(const unsigned int* __restrict__ raw, int* __restrict__ out,
                          int total_elems) {
    int i = blockIdx.x * blockDim.x + threadIdx.x;
    if (i >= total_elems) return;
    const int is64 = g_is64;
    out[i] = is64 ? (int)raw[2 * (size_t)i] : (int)raw[i];
}

// ---------------------------------------------------------------------------
// Degree kernels
// ---------------------------------------------------------------------------
__global__ void k_fill1(float* p, int n) {
    int i = blockIdx.x * blockDim.x + threadIdx.x;
    if (i < n) p[i] = 1.0f;  // self-loop contributes 1 to every node's degree
}

__global__ void k_deg_count(float* deg, const int* __restrict__ dst, int e) {
    int i = blockIdx.x * blockDim.x + threadIdx.x;
    if (i < e) atomicAdd(&deg[dst[i]], 1.0f);
}

__global__ void k_rsqrt(float* p, int n) {
    int i = blockIdx.x * blockDim.x + threadIdx.x;
    if (i < n) p[i] = rsqrtf(p[i]);
}

// ---------------------------------------------------------------------------
// GEMM: Y[n,128] = f(X)[n,128] @ W[128,128]
// MODE 0: f(x) = x         MODE 1: f(x) = relu(x + bias)  (fuses conv1 epilogue)
// BM=64 rows/block, BK=16, 256 threads, each thread -> 8 rows x 4 cols (float4)
// ---------------------------------------------------------------------------
template <int MODE>
__global__ __launch_bounds__(256) void k_gemm128(
    const float* __restrict__ X, const float* __restrict__ W,
    const float* __restrict__ bias, float* __restrict__ Y, int nrows)
{
    __shared__ float  xs[16][65];       // [k][row], +1 pad
    __shared__ float4 ws[16][32];       // [k][col/4]

    const int tid = threadIdx.x;
    const int tx  = tid & 31;           // col group (cols tx*4 .. tx*4+3)
    const int ty  = tid >> 5;           // row group (rows ty*8 .. ty*8+7)
    const int rowBase = blockIdx.x * 64;

    float4 acc[8];
#pragma unroll
    for (int r = 0; r < 8; r++) acc[r] = make_float4(0.f, 0.f, 0.f, 0.f);

    const int lrow = tid >> 2;          // 0..63
    const int lkv  = tid & 3;           // 0..3
    const int wk   = tid >> 5;          // 0..7
    const int wj   = tid & 31;          // 0..31

    for (int k0 = 0; k0 < 128; k0 += 16) {
        // --- load X tile (transposed into xs) ---
        float4 v = make_float4(0.f, 0.f, 0.f, 0.f);
        const int grow = rowBase + lrow;
        if (grow < nrows)
            v = reinterpret_cast<const float4*>(X)[(grow * 128 + k0 + lkv * 4) >> 2];
        if (MODE == 1) {
            const float4 bv = reinterpret_cast<const float4*>(bias)[(k0 + lkv * 4) >> 2];
            v.x = fmaxf(v.x + bv.x, 0.f);
            v.y = fmaxf(v.y + bv.y, 0.f);
            v.z = fmaxf(v.z + bv.z, 0.f);
            v.w = fmaxf(v.w + bv.w, 0.f);
        }
        xs[lkv * 4 + 0][lrow] = v.x;
        xs[lkv * 4 + 1][lrow] = v.y;
        xs[lkv * 4 + 2][lrow] = v.z;
        xs[lkv * 4 + 3][lrow] = v.w;
        // --- load W tile ---
        ws[wk][wj]     = reinterpret_cast<const float4*>(W)[((k0 + wk) * 128 + wj * 4) >> 2];
        ws[wk + 8][wj] = reinterpret_cast<const float4*>(W)[((k0 + wk + 8) * 128 + wj * 4) >> 2];
        __syncthreads();

#pragma unroll
        for (int kk = 0; kk < 16; kk++) {
            const float4 w = ws[kk][tx];
#pragma unroll
            for (int r = 0; r < 8; r++) {
                const float a = xs[kk][ty * 8 + r];
                acc[r].x = fmaf(a, w.x, acc[r].x);
                acc[r].y = fmaf(a, w.y, acc[r].y);
                acc[r].z = fmaf(a, w.z, acc[r].z);
                acc[r].w = fmaf(a, w.w, acc[r].w);
            }
        }
        __syncthreads();
    }

#pragma unroll
    for (int r = 0; r < 8; r++) {
        const int grow = rowBase + ty * 8 + r;
        if (grow < nrows)
            reinterpret_cast<float4*>(Y)[(grow * 128 + tx * 4) >> 2] = acc[r];
    }
}

// ---------------------------------------------------------------------------
// Self-loop init: agg[n][:] = h[n][:] * dinv[n]^2
// ---------------------------------------------------------------------------
__global__ void k_selfloop(const float4* __restrict__ h, float4* __restrict__ agg,
                           const float* __restrict__ dinv, int n32)
{
    int i = blockIdx.x * blockDim.x + threadIdx.x;
    if (i >= n32) return;
    const float di = dinv[i >> 5];
    const float s  = di * di;
    float4 v = h[i];
    v.x *= s; v.y *= s; v.z *= s; v.w *= s;
    agg[i] = v;
}

// ---------------------------------------------------------------------------
// Edge scatter: one warp per edge. agg[dst] += h[src] * dinv[src]*dinv[dst]
// 32 float4 vector reductions per edge (one per lane).
// ---------------------------------------------------------------------------
__global__ __launch_bounds__(256) void k_scatter(
    const float4* __restrict__ h, float4* __restrict__ agg,
    const int* __restrict__ src, const int* __restrict__ dst,
    const float* __restrict__ dinv, int e)
{
    const int eid = (int)((blockIdx.x * blockDim.x + threadIdx.x) >> 5);
    if (eid >= e) return;
    const int lane = threadIdx.x & 31;
    const int s = __ldg(&src[eid]);
    const int d = __ldg(&dst[eid]);
    const float nrm = __ldg(&dinv[s]) * __ldg(&dinv[d]);
    float4 v = h[s * 32 + lane];
    v.x *= nrm; v.y *= nrm; v.z *= nrm; v.w *= nrm;
    red_add_f4(agg + d * 32 + lane, v);
}

// ---------------------------------------------------------------------------
// Final epilogue: out_t[n][j] = agg[n][j] + b2[j]
// ---------------------------------------------------------------------------
__global__ void k_finalize(const float4* __restrict__ agg, const float* __restrict__ b2,
                           float* __restrict__ out, int n32)
{
    int i = blockIdx.x * blockDim.x + threadIdx.x;
    if (i >= n32) return;
    float4 v = agg[i];
    const float4 b = reinterpret_cast<const float4*>(b2)[i & 31];
    v.x += b.x; v.y += b.y; v.z += b.z; v.w += b.w;
    reinterpret_cast<float4*>(out)[i] = v;
}

// ---------------------------------------------------------------------------
// Importance: imp[n] = dot(out1[n,:], Wc) + bc   (one warp per node)
// ---------------------------------------------------------------------------
__global__ void k_importance(const float* __restrict__ out1, const float* __restrict__ Wc,
                             const float* __restrict__ bc, float* __restrict__ imp, int n)
{
    const int node = (int)((blockIdx.x * blockDim.x + threadIdx.x) >> 5);
    if (node >= n) return;
    const int lane = threadIdx.x & 31;
    const float4 a = reinterpret_cast<const float4*>(out1)[node * 32 + lane];
    const float4 w = reinterpret_cast<const float4*>(Wc)[lane];
    float s = a.x * w.x + a.y * w.y + a.z * w.z + a.w * w.w;
#pragma unroll
    for (int off = 16; off; off >>= 1) s += __shfl_xor_sync(0xffffffffu, s, off);
    if (lane == 0) imp[node] = s + bc[0];
}

// ---------------------------------------------------------------------------
// Launch
// ---------------------------------------------------------------------------
extern "C" void kernel_launch(void* const* d_in, const int* in_sizes, int n_in,
                              void* d_out, int out_size)
{
    const float*        x_seq = (const float*)d_in[0];        // [T, N, 128]
    const unsigned int* eraw  = (const unsigned int*)d_in[1]; // [T, 2, E] int32 or int64
    const float*        W1    = (const float*)d_in[2];
    const float*        b1    = (const float*)d_in[3];
    const float*        W2    = (const float*)d_in[4];
    const float*        b2    = (const float*)d_in[5];
    const float*        Wc    = (const float*)d_in[6];
    const float*        bc    = (const float*)d_in[7];

    const int N = in_sizes[0] / (TT * CDIM);
    const int E = in_sizes[1] / (TT * 2);
    const int n32 = N * 32;   // float4 elements per feature matrix
    const int totalE = TT * 2 * E;

    float* out  = (float*)d_out;
    float* imp  = out;          // [N]
    float* outs = out + N;      // out_t at outs + t*N*128

    float4* dh;  float4* dagg;  float* ddinv;  int* deidx;
    cudaGetSymbolAddress((void**)&dh,    g_h);
    cudaGetSymbolAddress((void**)&dagg,  g_agg);
    cudaGetSymbolAddress((void**)&ddinv, g_dinv);
    cudaGetSymbolAddress((void**)&deidx, g_eidx);

    const int TPB = 256;
    const int gN    = (N + TPB - 1) / TPB;
    const int gE    = (E + TPB - 1) / TPB;
    const int g32   = (n32 + TPB - 1) / TPB;
    const int gGemm = (N + 63) / 64;
    const int gScat = (E * 32 + TPB - 1) / TPB;   // one warp per edge
    const int gConv = (totalE + TPB - 1) / TPB;

    // Detect int32 vs int64 edge dtype, then materialize int32 indices.
    k_detect<<<1, 32>>>(eraw, totalE);
    k_convert<<<gConv, TPB>>>(eraw, deidx, totalE);

    for (int t = 0; t < TT; t++) {
        const int* src = deidx + (size_t)t * 2 * E;
        const int* dst = src + E;
        const float* x_t = x_seq + (size_t)t * N * CDIM;
        float* out_t = outs + (size_t)t * N * CDIM;

        // degree -> dinv
        k_fill1<<<gN, TPB>>>(ddinv, N);
        k_deg_count<<<gE, TPB>>>(ddinv, dst, E);
        k_rsqrt<<<gN, TPB>>>(ddinv, N);

        // conv1: h = x_t @ W1 ; agg = normalize-scatter(h)
        k_gemm128<0><<<gGemm, TPB>>>(x_t, W1, b1, (float*)dh, N);
        k_selfloop<<<g32, TPB>>>(dh, dagg, ddinv, n32);
        k_scatter<<<gScat, TPB>>>(dh, dagg, src, dst, ddinv, E);

        // conv2: h = relu(agg + b1) @ W2 ; agg = normalize-scatter(h)
        k_gemm128<1><<<gGemm, TPB>>>((const float*)dagg, W2, b1, (float*)dh, N);
        k_selfloop<<<g32, TPB>>>(dh, dagg, ddinv, n32);
        k_scatter<<<gScat, TPB>>>(dh, dagg, src, dst, ddinv, E);

        // out_t = agg + b2
        k_finalize<<<g32, TPB>>>(dagg, b2, out_t, n32);
    }

    // importance from last timestep's output
    k_importance<<<(N * 32 + TPB - 1) / TPB, TPB>>>(outs + (size_t)(TT - 1) * N * CDIM,
                                                    Wc, bc, imp, N);
}